// round 17
// baseline (speedup 1.0000x reference)
#include <cuda_runtime.h>
#include <cuda_fp16.h>
#include <cstdint>

#define N_WG   512
#define MPAIR  256
#define NCOL   512
#define N_NODE (NCOL * MPAIR)
#define BATCH  8192

// ===========================================================================
// Packed f32x2 helpers
// ===========================================================================
typedef unsigned long long F2;
__device__ __forceinline__ F2 pk(float lo, float hi) {
    F2 r; asm("mov.b64 %0, {%1, %2};" : "=l"(r) : "f"(lo), "f"(hi)); return r;
}
__device__ __forceinline__ void un2(F2 v, float& lo, float& hi) {
    asm("mov.b64 {%0, %1}, %2;" : "=f"(lo), "=f"(hi) : "l"(v));
}
__device__ __forceinline__ F2 splat(float a) { return pk(a, a); }
__device__ __forceinline__ F2 fma2(F2 a, F2 b, F2 c) {
    F2 d; asm("fma.rn.f32x2 %0, %1, %2, %3;" : "=l"(d) : "l"(a), "l"(b), "l"(c)); return d;
}
__device__ __forceinline__ F2 mul2(F2 a, F2 b) {
    F2 d; asm("mul.rn.f32x2 %0, %1, %2;" : "=l"(d) : "l"(a), "l"(b)); return d;
}
__device__ __forceinline__ float2 cmul(float2 a, float2 b) {
    return make_float2(a.x * b.x - a.y * b.y, a.x * b.y + a.y * b.x);
}
__device__ __forceinline__ float2 cadd(float2 a, float2 b) {
    return make_float2(a.x + b.x, a.y + b.y);
}
__device__ __forceinline__ uint32_t smem_u32(const void* p) {
    uint32_t a;
    asm("{ .reg .u64 t; cvta.to.shared.u64 t, %1; cvt.u32.u64 %0, t; }" : "=r"(a) : "l"(p));
    return a;
}

// ===========================================================================
// Static scratch
// ===========================================================================
__device__ float2 g_U00[N_NODE], g_U01[N_NODE], g_U10[N_NODE], g_U11[N_NODE];
__device__ __align__(16) __half g_G[1024 * 512];
__device__ __align__(16) __half g_X[512 * 8192];
__device__ __align__(16) __half g_S[1024 * 512];
__device__ __align__(16) __half g_B[1024 * 1024];
__device__ __align__(16) float g_Gp[4][1024 * 512];

// ===========================================================================
// Kernel 1 (fused): X fp32->fp16 conversion + per-node U build.
// ===========================================================================
__global__ __launch_bounds__(256) void prep_kernel(
        const float4* __restrict__ X4,
        const float* __restrict__ th, const float* __restrict__ ph,
        const float* __restrict__ bse, const float* __restrict__ lse) {
    if (blockIdx.x < 4096) {
        int i = blockIdx.x * 256 + threadIdx.x;
        float4 v = X4[i];
        __half2 h0, h1;
        h0.x = __float2half_rn(v.x); h0.y = __float2half_rn(v.y);
        h1.x = __float2half_rn(v.z); h1.y = __float2half_rn(v.w);
        __half2* X2 = reinterpret_cast<__half2*>(g_X);
        X2[2 * i] = h0; X2[2 * i + 1] = h1;
        return;
    }
    int idx = (blockIdx.x - 4096) * 256 + threadIdx.x;
    int c = idx >> 8;
    int p = idx & 255;
    bool msk = ((c & 1) == 0) || (p < MPAIR - 1);

    float2 U00 = {1.f, 0.f}, U01 = {0.f, 0.f}, U10 = {0.f, 0.f}, U11 = {1.f, 0.f};
    if (msk) {
        float theta = th[idx], phi = ph[idx];
        float e0 = bse[2 * idx], e1 = bse[2 * idx + 1];
        float l0 = lse[2 * idx], l1 = lse[2 * idx + 1];
        const float KL = 0.11512925464970229f;
        float ins0 = expf(l0 * KL), ins1 = expf(l1 * KL);
        const float PI4 = 0.7853981633974483f;
        float s0, c0, s1, c1;
        sincosf(PI4 + e0, &s0, &c0);
        sincosf(PI4 + e1, &s1, &c1);
        float2 EL, ET;
        sincosf(phi, &EL.y, &EL.x);
        sincosf(theta, &ET.y, &ET.x);
        float2 L11 = {ins0 * s0, 0.f}, L12 = {0.f, ins0 * c0}, L21 = {0.f, c0}, L22 = {s0, 0.f};
        float2 R11 = {ins1 * s1, 0.f}, R12 = {0.f, ins1 * c1}, R21 = {0.f, c1}, R22 = {s1, 0.f};
        float2 M00 = cmul(L11, cmul(EL, ET));
        float2 M10 = cmul(L12, EL);
        float2 M01 = cmul(L21, ET);
        float2 M11 = L22;
        U00 = cadd(cmul(R11, M00), cmul(R21, M10));
        U01 = cadd(cmul(R11, M01), cmul(R21, M11));
        U10 = cadd(cmul(R12, M00), cmul(R22, M10));
        U11 = cadd(cmul(R12, M01), cmul(R22, M11));
    }
    g_U00[idx] = U00; g_U01[idx] = U01; g_U10[idx] = U10; g_U11[idx] = U11;
}

// ===========================================================================
// Kernel 2: segmented propagation (proven). 2 segments x 256 cols.
// ===========================================================================
__device__ __forceinline__ void apply2(const F2* S, F2& tr, F2& ti, F2& br, F2& bi) {
    F2 ntr = fma2(S[5],  bi, fma2(S[3], br, fma2(S[2], ti, mul2(S[0], tr))));
    F2 nti = fma2(S[4],  br, fma2(S[3], bi, fma2(S[1], tr, mul2(S[0], ti))));
    F2 nbr = fma2(S[11], bi, fma2(S[9], br, fma2(S[8], ti, mul2(S[6], tr))));
    F2 nbi = fma2(S[10], br, fma2(S[9], bi, fma2(S[7], tr, mul2(S[6], ti))));
    tr = ntr; ti = nti; br = nbr; bi = nbi;
}

__device__ __forceinline__ void emitS(int row, int col, F2 v) {
    float x, y; un2(v, x, y);
    __half2 H; H.x = __float2half_rn(x); H.y = __float2half_rn(y);
    *reinterpret_cast<__half2*>(&g_S[(size_t)row * 512 + col]) = H;
}
__device__ __forceinline__ void emitB(int row, int col, F2 v, bool neg) {
    float x, y; un2(v, x, y);
    if (neg) { x = -x; y = -y; }
    __half2 H; H.x = __float2half_rn(x); H.y = __float2half_rn(y);
    *reinterpret_cast<__half2*>(&g_B[(size_t)row * 1024 + col]) = H;
}

__global__ __launch_bounds__(256, 2) void propagate(const float* __restrict__ gammas) {
    int r   = threadIdx.x;
    int bid = blockIdx.x;
    int seg = bid >> 7;
    int jb  = (bid & 127) * 4;
    int cbase = seg << 8;

    int i0 = 2 * r, i1 = 2 * r + 1;
    int lane = r & 31, w = r >> 5;

    float sg0 = 0.f, cg0 = 1.f, sg1 = 0.f, cg1 = 1.f;
    if (seg == 0) {
        sincosf(gammas[i0], &sg0, &cg0);
        sincosf(gammas[i1], &sg1, &cg1);
    }

    F2 are[2], aim[2], bre[2], bim[2];
#pragma unroll
    for (int k = 0; k < 2; k++) {
        int j0 = jb + 2 * k, j1 = j0 + 1;
        are[k] = pk(i0 == j0 ? cg0 : 0.f, i0 == j1 ? cg0 : 0.f);
        aim[k] = pk(i0 == j0 ? sg0 : 0.f, i0 == j1 ? sg0 : 0.f);
        bre[k] = pk(i1 == j0 ? cg1 : 0.f, i1 == j1 ? cg1 : 0.f);
        bim[k] = pk(i1 == j0 ? sg1 : 0.f, i1 == j1 ? sg1 : 0.f);
    }

    __shared__ F2 sEA[8][4];
    __shared__ F2 sEB[8][4];

    int ub = (cbase << 8) + r;
    float2 u00 = g_U00[ub], u01 = g_U01[ub], u10 = g_U10[ub], u11 = g_U11[ub];

    for (int c = 0; c < 256; c++) {
        float2 p00, p01, p10, p11;
        if (c + 1 < 256) {
            int nidx = ((cbase + c + 1) << 8) + r;
            p00 = g_U00[nidx]; p01 = g_U01[nidx]; p10 = g_U10[nidx]; p11 = g_U11[nidx];
        }
        F2 S[12] = {
            splat(u00.x), splat(u00.y), splat(-u00.y),
            splat(u01.x), splat(u01.y), splat(-u01.y),
            splat(u10.x), splat(u10.y), splat(-u10.y),
            splat(u11.x), splat(u11.y), splat(-u11.y)
        };
        if ((c & 1) == 0) {
#pragma unroll
            for (int k = 0; k < 2; k++)
                apply2(S, are[k], aim[k], bre[k], bim[k]);
        } else {
            F2 nar[2], nai[2];
#pragma unroll
            for (int k = 0; k < 2; k++) {
                nar[k] = __shfl_down_sync(0xffffffffu, are[k], 1);
                nai[k] = __shfl_down_sync(0xffffffffu, aim[k], 1);
            }
            if (lane == 0 && r > 0) {
                sEA[w][0] = are[0]; sEA[w][1] = are[1];
                sEA[w][2] = aim[0]; sEA[w][3] = aim[1];
            }
            __syncthreads();
            if (lane == 31 && r < 255) {
                nar[0] = sEA[w + 1][0]; nar[1] = sEA[w + 1][1];
                nai[0] = sEA[w + 1][2]; nai[1] = sEA[w + 1][3];
            }
            if (r < 255) {
#pragma unroll
                for (int k = 0; k < 2; k++)
                    apply2(S, bre[k], bim[k], nar[k], nai[k]);
            }
            F2 up0 = __shfl_up_sync(0xffffffffu, nar[0], 1);
            F2 up1 = __shfl_up_sync(0xffffffffu, nar[1], 1);
            F2 up2 = __shfl_up_sync(0xffffffffu, nai[0], 1);
            F2 up3 = __shfl_up_sync(0xffffffffu, nai[1], 1);
            if (lane == 31 && r < 255) {
                sEB[w + 1][0] = nar[0]; sEB[w + 1][1] = nar[1];
                sEB[w + 1][2] = nai[0]; sEB[w + 1][3] = nai[1];
            }
            __syncthreads();
            if (r > 0) {
                if (lane == 0) {
                    are[0] = sEB[w][0]; are[1] = sEB[w][1];
                    aim[0] = sEB[w][2]; aim[1] = sEB[w][3];
                } else {
                    are[0] = up0; are[1] = up1; aim[0] = up2; aim[1] = up3;
                }
            }
        }
        u00 = p00; u01 = p01; u10 = p10; u11 = p11;
    }

    if (seg == 0) {
#pragma unroll
        for (int k = 0; k < 2; k++) {
            int j0 = jb + 2 * k;
            emitS(i0,        j0, are[k]);
            emitS(512 + i0,  j0, aim[k]);
            emitS(i1,        j0, bre[k]);
            emitS(512 + i1,  j0, bim[k]);
        }
    } else {
#pragma unroll
        for (int k = 0; k < 2; k++) {
            int j0 = jb + 2 * k;
            emitB(i0,        j0,       are[k], false);
            emitB(i0,        512 + j0, aim[k], true);
            emitB(512 + i0,  j0,       aim[k], false);
            emitB(512 + i0,  512 + j0, are[k], false);
            emitB(i1,        j0,       bre[k], false);
            emitB(i1,        512 + j0, bim[k], true);
            emitB(512 + i1,  j0,       bim[k], false);
            emitB(512 + i1,  512 + j0, bre[k], false);
        }
    }
}

// ===========================================================================
// mma.sync fp16 primitives
// ===========================================================================
__device__ __forceinline__ void ldmx4(uint32_t* r, uint32_t addr) {
    asm volatile("ldmatrix.sync.aligned.m8n8.x4.shared.b16 {%0,%1,%2,%3}, [%4];"
                 : "=r"(r[0]), "=r"(r[1]), "=r"(r[2]), "=r"(r[3]) : "r"(addr));
}
__device__ __forceinline__ void ldmx4t(uint32_t* r, uint32_t addr) {
    asm volatile("ldmatrix.sync.aligned.m8n8.x4.trans.shared.b16 {%0,%1,%2,%3}, [%4];"
                 : "=r"(r[0]), "=r"(r[1]), "=r"(r[2]), "=r"(r[3]) : "r"(addr));
}
__device__ __forceinline__ void mma_f16(float* c, const uint32_t* a, uint32_t b0, uint32_t b1) {
    asm volatile("mma.sync.aligned.m16n8k16.row.col.f32.f16.f16.f32 "
                 "{%0,%1,%2,%3}, {%4,%5,%6,%7}, {%8,%9}, {%0,%1,%2,%3};"
                 : "+f"(c[0]), "+f"(c[1]), "+f"(c[2]), "+f"(c[3])
                 : "r"(a[0]), "r"(a[1]), "r"(a[2]), "r"(a[3]), "r"(b0), "r"(b1));
}

// ===========================================================================
// Kernel 3: compose GEMM, split-K (proven). grid (4, 8, 4).
// ===========================================================================
__global__ __launch_bounds__(256) void compose_gemm() {
    __shared__ __align__(1024) char raw[3 * 16384];
    uint32_t sbase = smem_u32(raw);

    int tid = threadIdx.x;
    int lane = tid & 31, wid = tid >> 5;
    int wm = wid & 3, wn = wid >> 2;
    int bm = blockIdx.y * 128, bn = blockIdx.x * 128;
    int kbase = blockIdx.z * 256;
    float* outp = g_Gp[blockIdx.z];

    auto issue = [&](int st, int buf) {
        int kblk = kbase + (st << 5);
        uint32_t base = sbase + buf * 16384;
#pragma unroll
        for (int h = 0; h < 2; h++) {
            int cA = tid + h * 256;
            int row = cA >> 2, kc = cA & 3;
            uint32_t dA = base + row * 64 + ((kc ^ ((row >> 1) & 3)) << 4);
            const __half* sA = g_B + (size_t)(bm + row) * 1024 + kblk + kc * 8;
            asm volatile("cp.async.cg.shared.global [%0], [%1], 16;" :: "r"(dA), "l"(sA));
            int cB = tid + h * 256;
            int k = cB >> 4, nch = cB & 15;
            uint32_t dB = base + 8192 + k * 256 + ((nch ^ (k & 7)) << 4);
            const __half* sB = g_S + (size_t)(kblk + k) * 512 + bn + nch * 8;
            asm volatile("cp.async.cg.shared.global [%0], [%1], 16;" :: "r"(dB), "l"(sB));
        }
        asm volatile("cp.async.commit_group;" ::: "memory");
    };

    int grp = lane >> 3, lrow = lane & 7;
    int g1 = grp & 1, g2 = grp >> 1;
    int arow = wm * 32 + g1 * 8 + lrow;
    uint32_t aBase = arow * 64 + ((g2 ^ (lrow >> 1)) << 4);
    int bk = g1 * 8 + lrow;
    uint32_t bBase = 8192 + bk * 256 + wn * 128 + ((g2 ^ lrow) << 4);

    float acc[2][8][4];
#pragma unroll
    for (int mt = 0; mt < 2; mt++)
#pragma unroll
        for (int nj = 0; nj < 8; nj++)
#pragma unroll
            for (int q = 0; q < 4; q++) acc[mt][nj][q] = 0.f;

    issue(0, 0);
    issue(1, 1);

#pragma unroll 1
    for (int st = 0; st < 8; st++) {
        int buf = st % 3;
        if (st < 7) asm volatile("cp.async.wait_group 1;" ::: "memory");
        else        asm volatile("cp.async.wait_group 0;" ::: "memory");
        __syncthreads();
        if (st + 2 < 8) issue(st + 2, (st + 2) % 3);

        uint32_t stage = sbase + buf * 16384;
#pragma unroll
        for (int s = 0; s < 2; s++) {
            uint32_t a[2][4];
            ldmx4(a[0], (stage + aBase) ^ (s << 5));
            ldmx4(a[1], (stage + aBase + 16 * 64) ^ (s << 5));
#pragma unroll
            for (int j2 = 0; j2 < 4; j2++) {
                uint32_t b[4];
                ldmx4t(b, (stage + bBase + (s << 12)) ^ (j2 << 5));
#pragma unroll
                for (int mt = 0; mt < 2; mt++) {
                    mma_f16(acc[mt][2 * j2],     a[mt], b[0], b[1]);
                    mma_f16(acc[mt][2 * j2 + 1], a[mt], b[2], b[3]);
                }
            }
        }
    }

    int mrow = bm + wm * 32 + (lane >> 2);
    int ncol = bn + wn * 64 + (lane & 3) * 2;
#pragma unroll
    for (int mt = 0; mt < 2; mt++) {
#pragma unroll
        for (int nj = 0; nj < 8; nj++) {
            float* o = outp + (size_t)(mrow + mt * 16) * 512 + ncol + nj * 8;
            *reinterpret_cast<float2*>(o)           = make_float2(acc[mt][nj][0], acc[mt][nj][1]);
            *reinterpret_cast<float2*>(o + 8 * 512) = make_float2(acc[mt][nj][2], acc[mt][nj][3]);
        }
    }
}

// ===========================================================================
// Kernel 3b: combine split-K partials -> g_G fp16.
// ===========================================================================
__global__ __launch_bounds__(256) void combine_kernel() {
    int i = (blockIdx.x * 256 + threadIdx.x) * 2;
    float a0 = g_Gp[0][i] + g_Gp[1][i] + g_Gp[2][i] + g_Gp[3][i];
    float a1 = g_Gp[0][i + 1] + g_Gp[1][i + 1] + g_Gp[2][i + 1] + g_Gp[3][i + 1];
    __half2 h; h.x = __float2half_rn(a0); h.y = __float2half_rn(a1);
    *reinterpret_cast<__half2*>(&g_G[i]) = h;
}

// ===========================================================================
// Kernel 4: final fp16 GEMM v2 — 512 threads / 16 warps, warp tile 32x32.
// Same 128x128 CTA tile, smem layout and swizzles as the proven 256-thread
// version; more warps per SM to feed the HMMA pipe.
// ===========================================================================
__global__ __launch_bounds__(512, 2) void mma_gemm(float* __restrict__ out) {
    __shared__ __align__(1024) char raw[3 * 16384];
    uint32_t sbase = smem_u32(raw);

    int tid = threadIdx.x;
    int lane = tid & 31, wid = tid >> 5;      // 16 warps
    int wm = wid & 3, wn = wid >> 2;          // 4 x 4 warp grid (32m x 32n each)
    int bm = blockIdx.y * 128, bn = blockIdx.x * 128;

    auto issue = [&](int st, int buf) {
        int kblk = st << 5;
        uint32_t base = sbase + buf * 16384;
        // A: one 16B per thread (128 rows x 4 chunks = 512)
        int rowA = tid >> 2, kc = tid & 3;
        uint32_t dA = base + rowA * 64 + ((kc ^ ((rowA >> 1) & 3)) << 4);
        const __half* sA = g_G + (size_t)(bm + rowA) * 512 + kblk + kc * 8;
        asm volatile("cp.async.cg.shared.global [%0], [%1], 16;" :: "r"(dA), "l"(sA));
        // B: one 16B per thread (32 k x 16 chunks = 512)
        int kB = tid >> 4, nch = tid & 15;
        uint32_t dB = base + 8192 + kB * 256 + ((nch ^ (kB & 7)) << 4);
        const __half* sB = g_X + (size_t)(kblk + kB) * 8192 + bn + nch * 8;
        asm volatile("cp.async.cg.shared.global [%0], [%1], 16;" :: "r"(dB), "l"(sB));
        asm volatile("cp.async.commit_group;" ::: "memory");
    };

    int grp = lane >> 3, lrow = lane & 7;
    int g1 = grp & 1, g2 = grp >> 1;
    int arow = wm * 32 + g1 * 8 + lrow;
    uint32_t aBase = arow * 64 + ((g2 ^ (lrow >> 1)) << 4);
    int bk = g1 * 8 + lrow;

    float acc[2][4][4];
#pragma unroll
    for (int mt = 0; mt < 2; mt++)
#pragma unroll
        for (int nj = 0; nj < 4; nj++)
#pragma unroll
            for (int q = 0; q < 4; q++) acc[mt][nj][q] = 0.f;

    issue(0, 0);
    issue(1, 1);

#pragma unroll 1
    for (int st = 0; st < 16; st++) {
        int buf = st % 3;
        if (st < 15) asm volatile("cp.async.wait_group 1;" ::: "memory");
        else         asm volatile("cp.async.wait_group 0;" ::: "memory");
        __syncthreads();
        if (st + 2 < 16) issue(st + 2, (st + 2) % 3);

        uint32_t stage = sbase + buf * 16384;
#pragma unroll
        for (int s = 0; s < 2; s++) {
            uint32_t a[2][4];
            ldmx4(a[0], (stage + aBase) ^ (s << 5));
            ldmx4(a[1], (stage + aBase + 16 * 64) ^ (s << 5));
#pragma unroll
            for (int j2 = 0; j2 < 2; j2++) {
                uint32_t b[4];
                uint32_t chunk = (uint32_t)((wn << 2) | (j2 << 1) | g2) ^ (uint32_t)lrow;
                uint32_t addrB = stage + 8192 + bk * 256 + (s << 12) + (chunk << 4);
                ldmx4t(b, addrB);
#pragma unroll
                for (int mt = 0; mt < 2; mt++) {
                    mma_f16(acc[mt][2 * j2],     a[mt], b[0], b[1]);
                    mma_f16(acc[mt][2 * j2 + 1], a[mt], b[2], b[3]);
                }
            }
        }
    }

    int mrow = bm + wm * 32 + (lane >> 2);
    int ncol = bn + wn * 32 + (lane & 3) * 2;
#pragma unroll
    for (int mt = 0; mt < 2; mt++) {
#pragma unroll
        for (int nj = 0; nj < 4; nj++) {
            float* o = out + (size_t)(mrow + mt * 16) * 8192 + ncol + nj * 8;
            *reinterpret_cast<float2*>(o)             = make_float2(acc[mt][nj][0], acc[mt][nj][1]);
            *reinterpret_cast<float2*>(o + 8 * 8192)  = make_float2(acc[mt][nj][2], acc[mt][nj][3]);
        }
    }
}

// ===========================================================================
// Launch
// ===========================================================================
extern "C" void kernel_launch(void* const* d_in, const int* in_sizes, int n_in,
                              void* d_out, int out_size) {
    const float* x      = (const float*)d_in[0];
    const float* thetas = (const float*)d_in[1];
    const float* phis   = (const float*)d_in[2];
    const float* gammas = (const float*)d_in[3];
    const float* bse    = (const float*)d_in[4];
    const float* lse    = (const float*)d_in[5];
    (void)in_sizes; (void)n_in; (void)out_size;

    prep_kernel<<<4096 + 512, 256>>>((const float4*)x, thetas, phis, bse, lse);
    propagate<<<256, 256>>>(gammas);
    compose_gemm<<<dim3(4, 8, 4), 256>>>();
    combine_kernel<<<1024, 256>>>();
    mma_gemm<<<dim3(64, 8), 512>>>((float*)d_out);
}